// round 16
// baseline (speedup 1.0000x reference)
#include <cuda_runtime.h>

// Problem-shape constants (dataset: N=500000 nodes, E=4000000 edges/depth, D=8)
#define MAXN 500000
#define MAXD 8
#define NW32 ((MAXN + 31) / 32)
#define TBS 256

// Scratch (allocation-free rule: __device__ globals)
__device__ float    g_y[(size_t)MAXN * 8];        // proc MLP output per node
__device__ float    g_seg[(size_t)MAXN * 8];      // segment-sum accumulator
__device__ int      g_idx[(size_t)MAXD * MAXN];   // per-depth active node lists
__device__ int      g_cnt[MAXD];                  // per-depth active counts
__device__ unsigned g_bit[(size_t)MAXD * NW32];   // per-depth active bitmaps

typedef unsigned long long u64;

__device__ __forceinline__ u64 pack2(float lo, float hi) {
    u64 r;
    asm("mov.b64 %0, {%1, %2};" : "=l"(r)
        : "r"(__float_as_uint(lo)), "r"(__float_as_uint(hi)));
    return r;
}
__device__ __forceinline__ void unpack2(u64 v, float& lo, float& hi) {
    unsigned int a, b;
    asm("mov.b64 {%0, %1}, %2;" : "=r"(a), "=r"(b) : "l"(v));
    lo = __uint_as_float(a);
    hi = __uint_as_float(b);
}
__device__ __forceinline__ u64 fma2(u64 a, u64 b, u64 c) {
    u64 d;
    asm("fma.rn.f32x2 %0, %1, %2, %3;" : "=l"(d) : "l"(a), "l"(b), "l"(c));
    return d;
}

// leaky_relu(v) == max(v, 0.01*v)
__device__ __forceinline__ float lrelu(float v) { return fmaxf(v, 0.01f * v); }

// First layer: out[16] = lrelu(in[IN] @ W + b)
template <int IN>
__device__ __forceinline__ void layer16(const float* __restrict__ in, float* __restrict__ out,
                                        const float* __restrict__ W, const float* __restrict__ b) {
    u64 acc[8];
    const ulonglong2* bp = reinterpret_cast<const ulonglong2*>(b);
#pragma unroll
    for (int q = 0; q < 4; q++) {
        ulonglong2 bv = bp[q];
        acc[2 * q]     = bv.x;
        acc[2 * q + 1] = bv.y;
    }
#pragma unroll
    for (int i = 0; i < IN; i++) {
        u64 xp = pack2(in[i], in[i]);
        const ulonglong2* wr = reinterpret_cast<const ulonglong2*>(W + i * 16);
#pragma unroll
        for (int q = 0; q < 4; q++) {
            ulonglong2 wv = wr[q];
            acc[2 * q]     = fma2(xp, wv.x, acc[2 * q]);
            acc[2 * q + 1] = fma2(xp, wv.y, acc[2 * q + 1]);
        }
    }
#pragma unroll
    for (int p = 0; p < 8; p++) {
        float lo, hi;
        unpack2(acc[p], lo, hi);
        out[2 * p]     = lrelu(lo);
        out[2 * p + 1] = lrelu(hi);
    }
}

// 3-layer MLP: IN -> 16 -> 32 -> 8, activation after every layer.
// Layers 2+3 FUSED in 8-output chunks: never materializes h1[32] (register-
// pressure fix; FP accumulation order identical to the unfused version).
template <int IN>
__device__ __forceinline__ void mlp3(const float* __restrict__ in, float* __restrict__ out,
                                     const float* __restrict__ s) {
    float h0[16];
    layer16<IN>(in, h0, s, s + IN * 16);

    const float* W1 = s + IN * 16 + 16;   // [16][32]
    const float* b1 = s + IN * 16 + 528;  // [32]
    const float* W2 = s + IN * 16 + 560;  // [32][8]
    const float* b2 = s + IN * 16 + 816;  // [8]

    u64 acc3[4];
    {
        const ulonglong2* b2p = reinterpret_cast<const ulonglong2*>(b2);
        ulonglong2 v0 = b2p[0], v1 = b2p[1];
        acc3[0] = v0.x; acc3[1] = v0.y; acc3[2] = v1.x; acc3[3] = v1.y;
    }

#pragma unroll
    for (int c = 0; c < 4; c++) {
        u64 acc2[4];
        {
            const ulonglong2* b1p = reinterpret_cast<const ulonglong2*>(b1 + c * 8);
            ulonglong2 v0 = b1p[0], v1 = b1p[1];
            acc2[0] = v0.x; acc2[1] = v0.y; acc2[2] = v1.x; acc2[3] = v1.y;
        }
#pragma unroll
        for (int i = 0; i < 16; i++) {
            u64 xp = pack2(h0[i], h0[i]);
            const ulonglong2* wr = reinterpret_cast<const ulonglong2*>(W1 + i * 32 + c * 8);
            ulonglong2 w0 = wr[0], w1 = wr[1];
            acc2[0] = fma2(xp, w0.x, acc2[0]);
            acc2[1] = fma2(xp, w0.y, acc2[1]);
            acc2[2] = fma2(xp, w1.x, acc2[2]);
            acc2[3] = fma2(xp, w1.y, acc2[3]);
        }
        float h1c[8];
#pragma unroll
        for (int p = 0; p < 4; p++) {
            float lo, hi;
            unpack2(acc2[p], lo, hi);
            h1c[2 * p]     = lrelu(lo);
            h1c[2 * p + 1] = lrelu(hi);
        }
#pragma unroll
        for (int j = 0; j < 8; j++) {
            u64 xp = pack2(h1c[j], h1c[j]);
            const ulonglong2* wr = reinterpret_cast<const ulonglong2*>(W2 + (c * 8 + j) * 8);
            ulonglong2 w0 = wr[0], w1 = wr[1];
            acc3[0] = fma2(xp, w0.x, acc3[0]);
            acc3[1] = fma2(xp, w0.y, acc3[1]);
            acc3[2] = fma2(xp, w1.x, acc3[2]);
            acc3[3] = fma2(xp, w1.y, acc3[3]);
        }
    }
#pragma unroll
    for (int p = 0; p < 4; p++) {
        float lo, hi;
        unpack2(acc3[p], lo, hi);
        out[2 * p]     = lrelu(lo);
        out[2 * p + 1] = lrelu(hi);
    }
}

__device__ __forceinline__ void cpsh(float* dst, const float* src, int n) {
    for (int i = threadIdx.x; i < n; i += TBS) dst[i] = src[i];
}

__device__ __forceinline__ void load_wset(float* s, int IN,
                                          const float* W0, const float* b0,
                                          const float* W1, const float* b1,
                                          const float* W2, const float* b2) {
    cpsh(s, W0, IN * 16);
    cpsh(s + IN * 16, b0, 16);
    cpsh(s + IN * 16 + 16, W1, 512);
    cpsh(s + IN * 16 + 528, b1, 32);
    cpsh(s + IN * 16 + 560, W2, 256);
    cpsh(s + IN * 16 + 816, b2, 8);
}

// ---------------------------------------------------------------------------
// Counters + per-depth active-list compaction + active bitmaps
// (masks are exact {0,1})
// ---------------------------------------------------------------------------
__global__ void zero_counts(int* cnt, int D) {
    if (threadIdx.x < D) cnt[threadIdx.x] = 0;
}

__global__ void build_lists(const float* __restrict__ masks, int N, int D,
                            int* __restrict__ idx, int* __restrict__ cnt,
                            unsigned* __restrict__ bit) {
    __shared__ int warp_base[8];
    __shared__ int blk_base;
    int i = blockIdx.x * blockDim.x + threadIdx.x;
    int lane = threadIdx.x & 31;
    int w = threadIdx.x >> 5;
    for (int d = 0; d < D; d++) {
        bool act = (i < N) && (masks[(size_t)d * N + i] != 0.0f);
        unsigned bal = __ballot_sync(0xffffffffu, act);
        if (lane == 0 && i < N) bit[(size_t)d * NW32 + (i >> 5)] = bal;
        int wcnt = __popc(bal);
        int wpre = __popc(bal & ((1u << lane) - 1u));
        if (lane == 0) warp_base[w] = wcnt;
        __syncthreads();
        if (threadIdx.x == 0) {
            int tot = 0;
#pragma unroll
            for (int k = 0; k < 8; k++) { int c = warp_base[k]; warp_base[k] = tot; tot += c; }
            blk_base = atomicAdd(&cnt[d], tot);
        }
        __syncthreads();
        if (act) idx[(size_t)d * N + blk_base + warp_base[w] + wpre] = i;
        __syncthreads();
    }
}

// ---------------------------------------------------------------------------
// Kernel 1: x = prepMLP(inputs); y = procMLP(x); seg = 0
// ---------------------------------------------------------------------------
__global__ void __launch_bounds__(TBS, 4)
prep_kernel(const float* __restrict__ inputs,
            const float* pW0, const float* pb0, const float* pW1,
            const float* pb1, const float* pW2, const float* pb2,
            const float* cW0, const float* cb0, const float* cW1,
            const float* cb1, const float* cW2, const float* cb2,
            float* __restrict__ x, float* __restrict__ y,
            float* __restrict__ seg, int N) {
    __shared__ __align__(16) float s[904 + 952];
    load_wset(s, 5, pW0, pb0, pW1, pb1, pW2, pb2);
    load_wset(s + 904, 8, cW0, cb0, cW1, cb1, cW2, cb2);
    __syncthreads();

    int i = blockIdx.x * blockDim.x + threadIdx.x;
    if (i >= N) return;

    float in[5];
#pragma unroll
    for (int k = 0; k < 5; k++) in[k] = inputs[(size_t)i * 5 + k];

    float xo[8];
    mlp3<5>(in, xo, s);
    float yo[8];
    mlp3<8>(xo, yo, s + 904);

    float4* xp = reinterpret_cast<float4*>(x + (size_t)i * 8);
    xp[0] = make_float4(xo[0], xo[1], xo[2], xo[3]);
    xp[1] = make_float4(xo[4], xo[5], xo[6], xo[7]);
    float4* yp = reinterpret_cast<float4*>(y + (size_t)i * 8);
    yp[0] = make_float4(yo[0], yo[1], yo[2], yo[3]);
    yp[1] = make_float4(yo[4], yo[5], yo[6], yo[7]);
    float4 z = make_float4(0.f, 0.f, 0.f, 0.f);
    float4* gp = reinterpret_cast<float4*>(seg + (size_t)i * 8);
    gp[0] = z;
    gp[1] = z;
}

// ---------------------------------------------------------------------------
// Kernel 2 (per depth): seg[dst] += y[src], skipping edges with inactive dst.
// 4 edges/thread, int4 index loads, batched scattered LDG.128 + RED.128.
// __launch_bounds__(256,8): regs<=32 -> 64 warps/SM (was 48 @ regs=38);
// kernel is latency-exposed at occ=67% with L1/L2 only ~68%.
// ---------------------------------------------------------------------------
__device__ __forceinline__ void red_add_v4(float* addr, float4 v) {
    asm volatile("red.global.add.v4.f32 [%0], {%1, %2, %3, %4};"
                 :: "l"(addr), "f"(v.x), "f"(v.y), "f"(v.z), "f"(v.w)
                 : "memory");
}

__global__ void __launch_bounds__(TBS, 8)
edge_kernel(const int* __restrict__ src, const int* __restrict__ dst,
            const unsigned* __restrict__ bit_d,
            const float* __restrict__ y, float* __restrict__ seg, int E) {
    int i = blockIdx.x * TBS + threadIdx.x;
    int e0 = i * 4;
    if (e0 >= E) return;

    int dI[4], sI[4];
    bool ok[4];
    if (e0 + 3 < E) {
        int4 d4 = __ldg(reinterpret_cast<const int4*>(dst) + i);
        int4 s4 = __ldg(reinterpret_cast<const int4*>(src) + i);
        dI[0] = d4.x; dI[1] = d4.y; dI[2] = d4.z; dI[3] = d4.w;
        sI[0] = s4.x; sI[1] = s4.y; sI[2] = s4.z; sI[3] = s4.w;
#pragma unroll
        for (int k = 0; k < 4; k++) ok[k] = true;
    } else {
#pragma unroll
        for (int k = 0; k < 4; k++) {
            ok[k] = (e0 + k) < E;
            dI[k] = ok[k] ? __ldg(dst + e0 + k) : 0;
            sI[k] = ok[k] ? __ldg(src + e0 + k) : 0;
        }
    }

    // bitmap probes (62KB footprint, cache-resident)
#pragma unroll
    for (int k = 0; k < 4; k++) {
        if (ok[k]) {
            unsigned wb = __ldg(bit_d + (dI[k] >> 5));
            ok[k] = (wb >> (dI[k] & 31)) & 1u;
        }
    }

    // scattered gathers, batched (independent LDG.128s in flight)
    float4 v[8];
#pragma unroll
    for (int k = 0; k < 4; k++) {
        if (ok[k]) {
            const float4* yp = reinterpret_cast<const float4*>(y + (size_t)sI[k] * 8);
            v[2 * k]     = __ldg(yp);
            v[2 * k + 1] = __ldg(yp + 1);
        }
    }

    // scattered reductions
#pragma unroll
    for (int k = 0; k < 4; k++) {
        if (ok[k]) {
            float* sp = seg + (size_t)dI[k] * 8;
            red_add_v4(sp, v[2 * k]);
            red_add_v4(sp + 4, v[2 * k + 1]);
        }
    }
}

// ---------------------------------------------------------------------------
// Kernel 3 (per depth, COMPACTED over active nodes): for i in idx[0..cnt):
//   t = seg[i]; seg[i] = 0;   (re-zero in place: active-dst rows are exactly
//                              the rows edges ever write)
//   x[i] += aggMLP(t); if do_next: y[i] = procMLP(x[i])
// ---------------------------------------------------------------------------
__global__ void __launch_bounds__(TBS, 4)
fuse_kernel(float* __restrict__ x, float* __restrict__ seg,
            float* __restrict__ y,
            const int* __restrict__ idx_d, const int* __restrict__ cnt_d,
            const float* aW0, const float* ab0, const float* aW1,
            const float* ab1, const float* aW2, const float* ab2,
            const float* cW0, const float* cb0, const float* cW1,
            const float* cb1, const float* cW2, const float* cb2,
            int do_next) {
    int M = __ldg(cnt_d);
    if ((int)(blockIdx.x * blockDim.x) >= M) return;  // whole block inactive

    __shared__ __align__(16) float s[952 * 2];
    load_wset(s, 8, aW0, ab0, aW1, ab1, aW2, ab2);
    load_wset(s + 952, 8, cW0, cb0, cW1, cb1, cW2, cb2);
    __syncthreads();

    int t = blockIdx.x * blockDim.x + threadIdx.x;
    if (t >= M) return;
    int i = __ldg(idx_d + t);

    float4* gp = reinterpret_cast<float4*>(seg + (size_t)i * 8);
    float4 a0 = gp[0];
    float4 a1 = gp[1];
    float4 z = make_float4(0.f, 0.f, 0.f, 0.f);
    gp[0] = z;  // reset for the next depth's accumulation
    gp[1] = z;

    float tin[8] = {a0.x, a0.y, a0.z, a0.w, a1.x, a1.y, a1.z, a1.w};
    float ao[8];
    mlp3<8>(tin, ao, s);

    float4* xp = reinterpret_cast<float4*>(x + (size_t)i * 8);
    float4 x0 = xp[0];
    float4 x1 = xp[1];
    float xo[8];
    xo[0] = x0.x + ao[0];
    xo[1] = x0.y + ao[1];
    xo[2] = x0.z + ao[2];
    xo[3] = x0.w + ao[3];
    xo[4] = x1.x + ao[4];
    xo[5] = x1.y + ao[5];
    xo[6] = x1.z + ao[6];
    xo[7] = x1.w + ao[7];
    xp[0] = make_float4(xo[0], xo[1], xo[2], xo[3]);
    xp[1] = make_float4(xo[4], xo[5], xo[6], xo[7]);

    if (do_next) {
        float yo[8];
        mlp3<8>(xo, yo, s + 952);
        float4* yp = reinterpret_cast<float4*>(y + (size_t)i * 8);
        yp[0] = make_float4(yo[0], yo[1], yo[2], yo[3]);
        yp[1] = make_float4(yo[4], yo[5], yo[6], yo[7]);
    }
}

// ---------------------------------------------------------------------------
// Launch
// ---------------------------------------------------------------------------
extern "C" void kernel_launch(void* const* d_in, const int* in_sizes, int n_in,
                              void* d_out, int out_size) {
    const float* inputs  = (const float*)d_in[0];
    const int*   adj_src = (const int*)d_in[1];
    const int*   adj_dst = (const int*)d_in[2];
    const float* masks   = (const float*)d_in[3];
    const float* w[18];
    for (int k = 0; k < 18; k++) w[k] = (const float*)d_in[4 + k];
    // w[0..5]=prep, w[6..11]=proc, w[12..17]=agg

    int N = in_sizes[0] / 5;
    int D = in_sizes[3] / N;
    int E = in_sizes[1] / D;

    float* x = (float*)d_out;
    float *y, *seg;
    int *idx, *cnt;
    unsigned* bit;
    cudaGetSymbolAddress((void**)&y, g_y);
    cudaGetSymbolAddress((void**)&seg, g_seg);
    cudaGetSymbolAddress((void**)&idx, g_idx);
    cudaGetSymbolAddress((void**)&cnt, g_cnt);
    cudaGetSymbolAddress((void**)&bit, g_bit);

    const int T = TBS;
    int nb = (N + T - 1) / T;
    int et = (E + 3) / 4;                      // one thread per 4 edges
    int eb = (et + T - 1) / T;

    zero_counts<<<1, 32>>>(cnt, D);
    build_lists<<<nb, T>>>(masks, N, D, idx, cnt, bit);

    prep_kernel<<<nb, T>>>(inputs,
                           w[0], w[1], w[2], w[3], w[4], w[5],
                           w[6], w[7], w[8], w[9], w[10], w[11],
                           x, y, seg, N);

    for (int d = 0; d < D; d++) {
        edge_kernel<<<eb, T>>>(adj_src + (size_t)d * E, adj_dst + (size_t)d * E,
                               bit + (size_t)d * NW32, y, seg, E);
        fuse_kernel<<<nb, T>>>(x, seg, y,
                               idx + (size_t)d * N, cnt + d,
                               w[12], w[13], w[14], w[15], w[16], w[17],
                               w[6], w[7], w[8], w[9], w[10], w[11],
                               d < D - 1 ? 1 : 0);
    }
}

// round 17
// speedup vs baseline: 1.2203x; 1.2203x over previous
#include <cuda_runtime.h>

// Problem-shape constants (dataset: N=500000 nodes, E=4000000 edges/depth, D=8)
#define MAXN 500000
#define MAXD 8
#define NW32 ((MAXN + 31) / 32)
#define TBS 256

// Scratch (allocation-free rule: __device__ globals)
__device__ float    g_y[(size_t)MAXN * 8];        // proc MLP output per node
__device__ float    g_seg[(size_t)MAXN * 8];      // segment-sum accumulator
__device__ int      g_idx[(size_t)MAXD * MAXN];   // per-depth active node lists
__device__ int      g_cnt[MAXD];                  // per-depth active counts
__device__ unsigned g_bit[(size_t)MAXD * NW32];   // per-depth active bitmaps

typedef unsigned long long u64;

__device__ __forceinline__ u64 pack2(float lo, float hi) {
    u64 r;
    asm("mov.b64 %0, {%1, %2};" : "=l"(r)
        : "r"(__float_as_uint(lo)), "r"(__float_as_uint(hi)));
    return r;
}
__device__ __forceinline__ void unpack2(u64 v, float& lo, float& hi) {
    unsigned int a, b;
    asm("mov.b64 {%0, %1}, %2;" : "=r"(a), "=r"(b) : "l"(v));
    lo = __uint_as_float(a);
    hi = __uint_as_float(b);
}
__device__ __forceinline__ u64 fma2(u64 a, u64 b, u64 c) {
    u64 d;
    asm("fma.rn.f32x2 %0, %1, %2, %3;" : "=l"(d) : "l"(a), "l"(b), "l"(c));
    return d;
}

// 256-bit global accesses (Blackwell sm_100+): one scattered row = one op.
__device__ __forceinline__ void ldg256(const float* p, float4& a, float4& b) {
    asm volatile("ld.global.v8.f32 {%0,%1,%2,%3,%4,%5,%6,%7}, [%8];"
                 : "=f"(a.x), "=f"(a.y), "=f"(a.z), "=f"(a.w),
                   "=f"(b.x), "=f"(b.y), "=f"(b.z), "=f"(b.w)
                 : "l"(p));
}
__device__ __forceinline__ void ldg256_nc(const float* p, float4& a, float4& b) {
    asm volatile("ld.global.nc.v8.f32 {%0,%1,%2,%3,%4,%5,%6,%7}, [%8];"
                 : "=f"(a.x), "=f"(a.y), "=f"(a.z), "=f"(a.w),
                   "=f"(b.x), "=f"(b.y), "=f"(b.z), "=f"(b.w)
                 : "l"(p));
}
__device__ __forceinline__ void stg256(float* p, float4 a, float4 b) {
    asm volatile("st.global.v8.f32 [%0], {%1,%2,%3,%4,%5,%6,%7,%8};"
                 :: "l"(p),
                    "f"(a.x), "f"(a.y), "f"(a.z), "f"(a.w),
                    "f"(b.x), "f"(b.y), "f"(b.z), "f"(b.w)
                 : "memory");
}

// leaky_relu(v) == max(v, 0.01*v)
__device__ __forceinline__ float lrelu(float v) { return fmaxf(v, 0.01f * v); }

// First layer: out[16] = lrelu(in[IN] @ W + b)
template <int IN>
__device__ __forceinline__ void layer16(const float* __restrict__ in, float* __restrict__ out,
                                        const float* __restrict__ W, const float* __restrict__ b) {
    u64 acc[8];
    const ulonglong2* bp = reinterpret_cast<const ulonglong2*>(b);
#pragma unroll
    for (int q = 0; q < 4; q++) {
        ulonglong2 bv = bp[q];
        acc[2 * q]     = bv.x;
        acc[2 * q + 1] = bv.y;
    }
#pragma unroll
    for (int i = 0; i < IN; i++) {
        u64 xp = pack2(in[i], in[i]);
        const ulonglong2* wr = reinterpret_cast<const ulonglong2*>(W + i * 16);
#pragma unroll
        for (int q = 0; q < 4; q++) {
            ulonglong2 wv = wr[q];
            acc[2 * q]     = fma2(xp, wv.x, acc[2 * q]);
            acc[2 * q + 1] = fma2(xp, wv.y, acc[2 * q + 1]);
        }
    }
#pragma unroll
    for (int p = 0; p < 8; p++) {
        float lo, hi;
        unpack2(acc[p], lo, hi);
        out[2 * p]     = lrelu(lo);
        out[2 * p + 1] = lrelu(hi);
    }
}

// 3-layer MLP: IN -> 16 -> 32 -> 8, activation after every layer.
// Layers 2+3 FUSED in 8-output chunks (register-pressure fix; FP order
// identical to the unfused version).
template <int IN>
__device__ __forceinline__ void mlp3(const float* __restrict__ in, float* __restrict__ out,
                                     const float* __restrict__ s) {
    float h0[16];
    layer16<IN>(in, h0, s, s + IN * 16);

    const float* W1 = s + IN * 16 + 16;   // [16][32]
    const float* b1 = s + IN * 16 + 528;  // [32]
    const float* W2 = s + IN * 16 + 560;  // [32][8]
    const float* b2 = s + IN * 16 + 816;  // [8]

    u64 acc3[4];
    {
        const ulonglong2* b2p = reinterpret_cast<const ulonglong2*>(b2);
        ulonglong2 v0 = b2p[0], v1 = b2p[1];
        acc3[0] = v0.x; acc3[1] = v0.y; acc3[2] = v1.x; acc3[3] = v1.y;
    }

#pragma unroll
    for (int c = 0; c < 4; c++) {
        u64 acc2[4];
        {
            const ulonglong2* b1p = reinterpret_cast<const ulonglong2*>(b1 + c * 8);
            ulonglong2 v0 = b1p[0], v1 = b1p[1];
            acc2[0] = v0.x; acc2[1] = v0.y; acc2[2] = v1.x; acc2[3] = v1.y;
        }
#pragma unroll
        for (int i = 0; i < 16; i++) {
            u64 xp = pack2(h0[i], h0[i]);
            const ulonglong2* wr = reinterpret_cast<const ulonglong2*>(W1 + i * 32 + c * 8);
            ulonglong2 w0 = wr[0], w1 = wr[1];
            acc2[0] = fma2(xp, w0.x, acc2[0]);
            acc2[1] = fma2(xp, w0.y, acc2[1]);
            acc2[2] = fma2(xp, w1.x, acc2[2]);
            acc2[3] = fma2(xp, w1.y, acc2[3]);
        }
        float h1c[8];
#pragma unroll
        for (int p = 0; p < 4; p++) {
            float lo, hi;
            unpack2(acc2[p], lo, hi);
            h1c[2 * p]     = lrelu(lo);
            h1c[2 * p + 1] = lrelu(hi);
        }
#pragma unroll
        for (int j = 0; j < 8; j++) {
            u64 xp = pack2(h1c[j], h1c[j]);
            const ulonglong2* wr = reinterpret_cast<const ulonglong2*>(W2 + (c * 8 + j) * 8);
            ulonglong2 w0 = wr[0], w1 = wr[1];
            acc3[0] = fma2(xp, w0.x, acc3[0]);
            acc3[1] = fma2(xp, w0.y, acc3[1]);
            acc3[2] = fma2(xp, w1.x, acc3[2]);
            acc3[3] = fma2(xp, w1.y, acc3[3]);
        }
    }
#pragma unroll
    for (int p = 0; p < 4; p++) {
        float lo, hi;
        unpack2(acc3[p], lo, hi);
        out[2 * p]     = lrelu(lo);
        out[2 * p + 1] = lrelu(hi);
    }
}

__device__ __forceinline__ void cpsh(float* dst, const float* src, int n) {
    for (int i = threadIdx.x; i < n; i += TBS) dst[i] = src[i];
}

__device__ __forceinline__ void load_wset(float* s, int IN,
                                          const float* W0, const float* b0,
                                          const float* W1, const float* b1,
                                          const float* W2, const float* b2) {
    cpsh(s, W0, IN * 16);
    cpsh(s + IN * 16, b0, 16);
    cpsh(s + IN * 16 + 16, W1, 512);
    cpsh(s + IN * 16 + 528, b1, 32);
    cpsh(s + IN * 16 + 560, W2, 256);
    cpsh(s + IN * 16 + 816, b2, 8);
}

// ---------------------------------------------------------------------------
// Counters + per-depth active-list compaction + active bitmaps
// (masks are exact {0,1})
// ---------------------------------------------------------------------------
__global__ void zero_counts(int* cnt, int D) {
    if (threadIdx.x < D) cnt[threadIdx.x] = 0;
}

__global__ void build_lists(const float* __restrict__ masks, int N, int D,
                            int* __restrict__ idx, int* __restrict__ cnt,
                            unsigned* __restrict__ bit) {
    __shared__ int warp_base[8];
    __shared__ int blk_base;
    int i = blockIdx.x * blockDim.x + threadIdx.x;
    int lane = threadIdx.x & 31;
    int w = threadIdx.x >> 5;
    for (int d = 0; d < D; d++) {
        bool act = (i < N) && (masks[(size_t)d * N + i] != 0.0f);
        unsigned bal = __ballot_sync(0xffffffffu, act);
        if (lane == 0 && i < N) bit[(size_t)d * NW32 + (i >> 5)] = bal;
        int wcnt = __popc(bal);
        int wpre = __popc(bal & ((1u << lane) - 1u));
        if (lane == 0) warp_base[w] = wcnt;
        __syncthreads();
        if (threadIdx.x == 0) {
            int tot = 0;
#pragma unroll
            for (int k = 0; k < 8; k++) { int c = warp_base[k]; warp_base[k] = tot; tot += c; }
            blk_base = atomicAdd(&cnt[d], tot);
        }
        __syncthreads();
        if (act) idx[(size_t)d * N + blk_base + warp_base[w] + wpre] = i;
        __syncthreads();
    }
}

// ---------------------------------------------------------------------------
// Kernel 1: x = prepMLP(inputs); y = procMLP(x); seg = 0
// ---------------------------------------------------------------------------
__global__ void __launch_bounds__(TBS, 4)
prep_kernel(const float* __restrict__ inputs,
            const float* pW0, const float* pb0, const float* pW1,
            const float* pb1, const float* pW2, const float* pb2,
            const float* cW0, const float* cb0, const float* cW1,
            const float* cb1, const float* cW2, const float* cb2,
            float* __restrict__ x, float* __restrict__ y,
            float* __restrict__ seg, int N) {
    __shared__ __align__(16) float s[904 + 952];
    load_wset(s, 5, pW0, pb0, pW1, pb1, pW2, pb2);
    load_wset(s + 904, 8, cW0, cb0, cW1, cb1, cW2, cb2);
    __syncthreads();

    int i = blockIdx.x * blockDim.x + threadIdx.x;
    if (i >= N) return;

    float in[5];
#pragma unroll
    for (int k = 0; k < 5; k++) in[k] = inputs[(size_t)i * 5 + k];

    float xo[8];
    mlp3<5>(in, xo, s);
    float yo[8];
    mlp3<8>(xo, yo, s + 904);

    stg256(x + (size_t)i * 8,
           make_float4(xo[0], xo[1], xo[2], xo[3]),
           make_float4(xo[4], xo[5], xo[6], xo[7]));
    stg256(y + (size_t)i * 8,
           make_float4(yo[0], yo[1], yo[2], yo[3]),
           make_float4(yo[4], yo[5], yo[6], yo[7]));
    float4 z = make_float4(0.f, 0.f, 0.f, 0.f);
    stg256(seg + (size_t)i * 8, z, z);
}

// ---------------------------------------------------------------------------
// Kernel 2 (per depth): seg[dst] += y[src], skipping edges with inactive dst.
// 4 edges/thread, int4 index loads, 256-bit scattered gathers (1 LDG.256 per
// row), RED.128 x2 scatters.
// ---------------------------------------------------------------------------
__device__ __forceinline__ void red_add_v4(float* addr, float4 v) {
    asm volatile("red.global.add.v4.f32 [%0], {%1, %2, %3, %4};"
                 :: "l"(addr), "f"(v.x), "f"(v.y), "f"(v.z), "f"(v.w)
                 : "memory");
}

__global__ void edge_kernel(const int* __restrict__ src, const int* __restrict__ dst,
                            const unsigned* __restrict__ bit_d,
                            const float* __restrict__ y, float* __restrict__ seg, int E) {
    int i = blockIdx.x * TBS + threadIdx.x;
    int e0 = i * 4;
    if (e0 >= E) return;

    int dI[4], sI[4];
    bool ok[4];
    if (e0 + 3 < E) {
        int4 d4 = __ldg(reinterpret_cast<const int4*>(dst) + i);
        int4 s4 = __ldg(reinterpret_cast<const int4*>(src) + i);
        dI[0] = d4.x; dI[1] = d4.y; dI[2] = d4.z; dI[3] = d4.w;
        sI[0] = s4.x; sI[1] = s4.y; sI[2] = s4.z; sI[3] = s4.w;
#pragma unroll
        for (int k = 0; k < 4; k++) ok[k] = true;
    } else {
#pragma unroll
        for (int k = 0; k < 4; k++) {
            ok[k] = (e0 + k) < E;
            dI[k] = ok[k] ? __ldg(dst + e0 + k) : 0;
            sI[k] = ok[k] ? __ldg(src + e0 + k) : 0;
        }
    }

    // bitmap probes (62KB footprint, cache-resident)
#pragma unroll
    for (int k = 0; k < 4; k++) {
        if (ok[k]) {
            unsigned wb = __ldg(bit_d + (dI[k] >> 5));
            ok[k] = (wb >> (dI[k] & 31)) & 1u;
        }
    }

    // scattered gathers, batched, one 256-bit load per row
    float4 v[8];
#pragma unroll
    for (int k = 0; k < 4; k++) {
        if (ok[k])
            ldg256_nc(y + (size_t)sI[k] * 8, v[2 * k], v[2 * k + 1]);
    }

    // scattered reductions
#pragma unroll
    for (int k = 0; k < 4; k++) {
        if (ok[k]) {
            float* sp = seg + (size_t)dI[k] * 8;
            red_add_v4(sp, v[2 * k]);
            red_add_v4(sp + 4, v[2 * k + 1]);
        }
    }
}

// ---------------------------------------------------------------------------
// Kernel 3 (per depth, COMPACTED over active nodes): for i in idx[0..cnt):
//   t = seg[i]; seg[i] = 0;  x[i] += aggMLP(t);
//   if do_next: y[i] = procMLP(x[i])
// All scattered row accesses are single 256-bit ops.
// ---------------------------------------------------------------------------
__global__ void __launch_bounds__(TBS, 4)
fuse_kernel(float* __restrict__ x, float* __restrict__ seg,
            float* __restrict__ y,
            const int* __restrict__ idx_d, const int* __restrict__ cnt_d,
            const float* aW0, const float* ab0, const float* aW1,
            const float* ab1, const float* aW2, const float* ab2,
            const float* cW0, const float* cb0, const float* cW1,
            const float* cb1, const float* cW2, const float* cb2,
            int do_next) {
    int M = __ldg(cnt_d);
    if ((int)(blockIdx.x * blockDim.x) >= M) return;  // whole block inactive

    __shared__ __align__(16) float s[952 * 2];
    load_wset(s, 8, aW0, ab0, aW1, ab1, aW2, ab2);
    load_wset(s + 952, 8, cW0, cb0, cW1, cb1, cW2, cb2);
    __syncthreads();

    int t = blockIdx.x * blockDim.x + threadIdx.x;
    if (t >= M) return;
    int i = __ldg(idx_d + t);

    float4 a0, a1;
    ldg256(seg + (size_t)i * 8, a0, a1);
    float4 z = make_float4(0.f, 0.f, 0.f, 0.f);
    stg256(seg + (size_t)i * 8, z, z);  // reset for next depth

    float tin[8] = {a0.x, a0.y, a0.z, a0.w, a1.x, a1.y, a1.z, a1.w};
    float ao[8];
    mlp3<8>(tin, ao, s);

    float4 x0, x1;
    ldg256(x + (size_t)i * 8, x0, x1);
    float xo[8];
    xo[0] = x0.x + ao[0];
    xo[1] = x0.y + ao[1];
    xo[2] = x0.z + ao[2];
    xo[3] = x0.w + ao[3];
    xo[4] = x1.x + ao[4];
    xo[5] = x1.y + ao[5];
    xo[6] = x1.z + ao[6];
    xo[7] = x1.w + ao[7];
    stg256(x + (size_t)i * 8,
           make_float4(xo[0], xo[1], xo[2], xo[3]),
           make_float4(xo[4], xo[5], xo[6], xo[7]));

    if (do_next) {
        float yo[8];
        mlp3<8>(xo, yo, s + 952);
        stg256(y + (size_t)i * 8,
               make_float4(yo[0], yo[1], yo[2], yo[3]),
               make_float4(yo[4], yo[5], yo[6], yo[7]));
    }
}

// ---------------------------------------------------------------------------
// Launch
// ---------------------------------------------------------------------------
extern "C" void kernel_launch(void* const* d_in, const int* in_sizes, int n_in,
                              void* d_out, int out_size) {
    const float* inputs  = (const float*)d_in[0];
    const int*   adj_src = (const int*)d_in[1];
    const int*   adj_dst = (const int*)d_in[2];
    const float* masks   = (const float*)d_in[3];
    const float* w[18];
    for (int k = 0; k < 18; k++) w[k] = (const float*)d_in[4 + k];
    // w[0..5]=prep, w[6..11]=proc, w[12..17]=agg

    int N = in_sizes[0] / 5;
    int D = in_sizes[3] / N;
    int E = in_sizes[1] / D;

    float* x = (float*)d_out;
    float *y, *seg;
    int *idx, *cnt;
    unsigned* bit;
    cudaGetSymbolAddress((void**)&y, g_y);
    cudaGetSymbolAddress((void**)&seg, g_seg);
    cudaGetSymbolAddress((void**)&idx, g_idx);
    cudaGetSymbolAddress((void**)&cnt, g_cnt);
    cudaGetSymbolAddress((void**)&bit, g_bit);

    const int T = TBS;
    int nb = (N + T - 1) / T;
    int et = (E + 3) / 4;                      // one thread per 4 edges
    int eb = (et + T - 1) / T;

    zero_counts<<<1, 32>>>(cnt, D);
    build_lists<<<nb, T>>>(masks, N, D, idx, cnt, bit);

    prep_kernel<<<nb, T>>>(inputs,
                           w[0], w[1], w[2], w[3], w[4], w[5],
                           w[6], w[7], w[8], w[9], w[10], w[11],
                           x, y, seg, N);

    for (int d = 0; d < D; d++) {
        edge_kernel<<<eb, T>>>(adj_src + (size_t)d * E, adj_dst + (size_t)d * E,
                               bit + (size_t)d * NW32, y, seg, E);
        fuse_kernel<<<nb, T>>>(x, seg, y,
                               idx + (size_t)d * N, cnt + d,
                               w[12], w[13], w[14], w[15], w[16], w[17],
                               w[6], w[7], w[8], w[9], w[10], w[11],
                               d < D - 1 ? 1 : 0);
    }
}